// round 14
// baseline (speedup 1.0000x reference)
#include <cuda_runtime.h>
#include <cstddef>

#define N_ROWS 4096
#define CH     256
#define NC     1000
#define NTILE  10      // upper-triangle 64x64 tiles of 256x256
#define NSPLIT 32      // K-splits of depth 128 over K=4096

// ---- scratch (static device globals; no runtime allocation) ----
__device__ float g_invn[N_ROWS];
__device__ float g_xn[N_ROWS * CH];                // D^-1 X (normalized rows)
__device__ float g_G[CH * CH];                     // full (mirrored) gram
__device__ float g_part[NTILE * NSPLIT * 64 * 64]; // 5.2 MB partial tiles
__device__ float g_s[NC * CH];                     // per-class sum invn_r * x_r
__device__ float g_t[NC * CH];                     // per-class sum x_r
__device__ float g_counts[NC];
__device__ unsigned int g_flagP;                   // prep-done   (K_A internal)
__device__ unsigned int g_flagR;                   // redG-done   (K_B internal)
__device__ unsigned int g_flagC;                   // proto-done  (K_B internal)

__constant__ int c_ti[NTILE] = {0,0,0,0,1,1,1,2,2,3};
__constant__ int c_tj[NTILE] = {0,1,2,3,1,2,3,2,3,3};

// ---------------------------------------------------------------
// K_A: prep -> (gram partials | argmax+scatter), staged via flagP.
//  b in [0,512):      norms + write Xn rows (8 rows/block)       -> flagP++
//  b in [512,762):    zero g_s                                   -> flagP++
//  b in [762,1012):   zero g_t                                   -> flagP++
//  b == 1012:         zero counts, reset flagR/flagC             -> flagP++
//  b in [1013,1333):  spin flagP==1013, gram 64x64 tile, K=128
//  b in [1333,1845):  spin flagP==1013, warp-per-row argmax + scatter
// Safe: 1013 prep blocks all fit in wave 1 (8 blocks/SM x 148 SM).
// ---------------------------------------------------------------
__global__ void __launch_bounds__(256) k_stage1(const float* __restrict__ x,
                                                const float* __restrict__ lg) {
    __shared__ float smem[2048];
    int b = blockIdx.x;
    int tid = threadIdx.x;

    if (b < 1013) {
        if (b < 512) {
            int warp = ((b << 8) + tid) >> 5;       // 0..4095
            int lane = tid & 31;
            const float4* p = (const float4*)(x + (size_t)warp * CH);
            float4 v0 = p[lane];
            float4 v1 = p[lane + 32];
            float ss = v0.x * v0.x + v0.y * v0.y + v0.z * v0.z + v0.w * v0.w
                     + v1.x * v1.x + v1.y * v1.y + v1.z * v1.z + v1.w * v1.w;
#pragma unroll
            for (int off = 16; off; off >>= 1)
                ss += __shfl_xor_sync(0xffffffffu, ss, off);
            float inv = rsqrtf(ss);
            float4* xn4 = (float4*)(g_xn + (size_t)warp * CH);
            xn4[lane]      = make_float4(v0.x * inv, v0.y * inv, v0.z * inv, v0.w * inv);
            xn4[lane + 32] = make_float4(v1.x * inv, v1.y * inv, v1.z * inv, v1.w * inv);
            if (lane == 0) g_invn[warp] = inv;
        } else if (b < 762) {
            ((float4*)g_s)[(b - 512) * 256 + tid] = make_float4(0.f, 0.f, 0.f, 0.f);
        } else if (b < 1012) {
            ((float4*)g_t)[(b - 762) * 256 + tid] = make_float4(0.f, 0.f, 0.f, 0.f);
        } else {
            for (int i = tid; i < NC; i += 256) g_counts[i] = 0.0f;
            if (tid == 0) { g_flagR = 0u; g_flagC = 0u; }
        }
        __threadfence();
        __syncthreads();
        if (tid == 0) atomicAdd(&g_flagP, 1u);
    } else if (b < 1333) {
        if (tid == 0) { while (atomicAdd(&g_flagP, 0u) < 1013u) { } }
        __syncthreads();

        float* As = smem;            // [16][64] : Xn[k][i-tile]
        float* Bs = smem + 1024;     // [16][64] : X [k][j-tile]
        int bb_ = b - 1013;
        int tile = bb_ >> 5;         // 0..9
        int k0 = (bb_ & 31) * 128;   // split * 128
        int i0 = c_ti[tile] * 64, j0 = c_tj[tile] * 64;
        int tx = tid & 15, ty = tid >> 4;

        float acc[4][4] = {};
#pragma unroll
        for (int kc = 0; kc < 128; kc += 16) {
#pragma unroll
            for (int l = 0; l < 4; l++) {
                int idx = tid + l * 256;          // 0..1023
                int kl = idx >> 6, col = idx & 63;
                int k = k0 + kc + kl;
                As[kl * 64 + col] = g_xn[(size_t)k * CH + i0 + col];
                Bs[kl * 64 + col] = x   [(size_t)k * CH + j0 + col];
            }
            __syncthreads();
            const float4* As4 = (const float4*)As;
            const float4* Bs4 = (const float4*)Bs;
#pragma unroll
            for (int kl = 0; kl < 16; kl++) {
                float4 a = As4[kl * 16 + ty];
                float4 bb = Bs4[kl * 16 + tx];
                acc[0][0] += a.x * bb.x; acc[0][1] += a.x * bb.y;
                acc[0][2] += a.x * bb.z; acc[0][3] += a.x * bb.w;
                acc[1][0] += a.y * bb.x; acc[1][1] += a.y * bb.y;
                acc[1][2] += a.y * bb.z; acc[1][3] += a.y * bb.w;
                acc[2][0] += a.z * bb.x; acc[2][1] += a.z * bb.y;
                acc[2][2] += a.z * bb.z; acc[2][3] += a.z * bb.w;
                acc[3][0] += a.w * bb.x; acc[3][1] += a.w * bb.y;
                acc[3][2] += a.w * bb.z; acc[3][3] += a.w * bb.w;
            }
            __syncthreads();
        }
        float4* p4 = (float4*)(g_part + (size_t)bb_ * 4096);
#pragma unroll
        for (int u = 0; u < 4; u++)
            p4[(ty * 4 + u) * 16 + tx] =
                make_float4(acc[u][0], acc[u][1], acc[u][2], acc[u][3]);
    } else {
        if (tid == 0) { while (atomicAdd(&g_flagP, 0u) < 1013u) { } }
        __syncthreads();

        // ---- warp-per-row argmax + scatter, 8 rows per block ----
        int row = ((b - 1333) << 3) + (tid >> 5);
        int lane = tid & 31;
        const float4* p = (const float4*)(lg + (size_t)row * NC);  // 250 float4
        float best = -3.4e38f;
        int   bi = 0;
#pragma unroll
        for (int i = 0; i < 8; i++) {
            int idx = lane + (i << 5);
            if (idx < 250) {
                float4 v = p[idx];
                int c = idx << 2;
                if (v.x > best) { best = v.x; bi = c; }
                if (v.y > best) { best = v.y; bi = c + 1; }
                if (v.z > best) { best = v.z; bi = c + 2; }
                if (v.w > best) { best = v.w; bi = c + 3; }
            }
        }
#pragma unroll
        for (int off = 16; off; off >>= 1) {
            float ov = __shfl_xor_sync(0xffffffffu, best, off);
            int   oi = __shfl_xor_sync(0xffffffffu, bi,   off);
            if (ov > best || (ov == best && oi < bi)) { best = ov; bi = oi; }
        }
        int cls = bi;
        float inv = g_invn[row];
        const float4* px = (const float4*)(x + (size_t)row * CH);
#pragma unroll
        for (int j = 0; j < 2; j++) {
            int idx4 = lane + (j << 5);           // 0..63
            float4 xv = px[idx4];
            int base = cls * CH + (idx4 << 2);
            atomicAdd(&g_s[base + 0], xv.x * inv);
            atomicAdd(&g_s[base + 1], xv.y * inv);
            atomicAdd(&g_s[base + 2], xv.z * inv);
            atomicAdd(&g_s[base + 3], xv.w * inv);
            atomicAdd(&g_t[base + 0], xv.x);
            atomicAdd(&g_t[base + 1], xv.y);
            atomicAdd(&g_t[base + 2], xv.z);
            atomicAdd(&g_t[base + 3], xv.w);
        }
        if (lane == 0) atomicAdd(&g_counts[cls], 1.0f);
    }
}

// ---------------------------------------------------------------
// K_B: redG -> proto -> inter, staged via flagR / flagC.
//  b in [0,40):    reduce g_part -> g_G (+ mirror)          -> flagR++
//  b in [40,540):  proto (2 classes/block, MLP-8 batches),
//                  spin flagR==40                           -> flagC++
//  b in [540,...): inter tile, spin flagC==500
// Safe: 540 non-inter blocks all fit in wave 1 (6 blocks/SM @ 33 KB smem).
// ---------------------------------------------------------------
__global__ void __launch_bounds__(256) k_stage2(float* __restrict__ proto,
                                                float* __restrict__ inter) {
    __shared__ float4 smem4[2064];     // 33 KB: inter pi/pj; proto s_sm/red
    int b = blockIdx.x;
    int tid = threadIdx.x;

    if (b == 0 && tid == 0) g_flagP = 0u;   // reset for next graph replay

    if (b < 40) {
        int idx = b * 256 + tid;                 // 0..10239
        int tile = idx >> 10;
        int p4i  = idx & 1023;
        int i0 = c_ti[tile] * 64, j0 = c_tj[tile] * 64;

        const float4* part4 = (const float4*)g_part;
        float4 sum = make_float4(0.f, 0.f, 0.f, 0.f);
#pragma unroll 8
        for (int s = 0; s < NSPLIT; s++) {
            float4 v = part4[(size_t)((tile << 5) + s) * 1024 + p4i];
            sum.x += v.x; sum.y += v.y; sum.z += v.z; sum.w += v.w;
        }
        int il = p4i >> 4;
        int jb = (p4i & 15) << 2;
        int i = i0 + il, j = j0 + jb;
        ((float4*)g_G)[(i * CH + j) >> 2] = sum;
        if (i0 != j0) {
            g_G[(j + 0) * CH + i] = sum.x;
            g_G[(j + 1) * CH + i] = sum.y;
            g_G[(j + 2) * CH + i] = sum.z;
            g_G[(j + 3) * CH + i] = sum.w;
        }
        __threadfence();
        __syncthreads();
        if (tid == 0) atomicAdd(&g_flagR, 1u);
    } else if (b < 540) {
        // ---- proto: 2 classes per block ----
        float*  s_sm = (float*)smem4;            // 512 floats
        float4* red  = smem4 + 128;              // 128 float4
        int c0 = (b - 40) * 2;
        int cgrp = tid >> 7;          // 0..1 class within block
        int sub  = (tid >> 6) & 1;    // k-half
        int col4 = tid & 63;          // float4 column group

        s_sm[tid]       = g_s[(size_t)c0 * CH + tid];
        s_sm[tid + 256] = g_s[(size_t)c0 * CH + tid + 256];
        if (tid == 0) { while (atomicAdd(&g_flagR, 0u) < 40u) { } }
        __syncthreads();

        const float4* Gp = (const float4*)g_G + (size_t)(sub * 128) * 64 + col4;
        const float*  sr = s_sm + cgrp * 256 + sub * 128;
        float4 acc = make_float4(0.f, 0.f, 0.f, 0.f);
#pragma unroll
        for (int kb = 0; kb < 128; kb += 8) {
            float4 g0 = Gp[(kb + 0) * 64];
            float4 g1 = Gp[(kb + 1) * 64];
            float4 g2 = Gp[(kb + 2) * 64];
            float4 g3 = Gp[(kb + 3) * 64];
            float4 g4 = Gp[(kb + 4) * 64];
            float4 g5 = Gp[(kb + 5) * 64];
            float4 g6 = Gp[(kb + 6) * 64];
            float4 g7 = Gp[(kb + 7) * 64];
            float s0 = sr[kb + 0], s1 = sr[kb + 1], s2 = sr[kb + 2], s3 = sr[kb + 3];
            float s4 = sr[kb + 4], s5 = sr[kb + 5], s6 = sr[kb + 6], s7 = sr[kb + 7];
            acc.x += s0 * g0.x; acc.y += s0 * g0.y; acc.z += s0 * g0.z; acc.w += s0 * g0.w;
            acc.x += s1 * g1.x; acc.y += s1 * g1.y; acc.z += s1 * g1.z; acc.w += s1 * g1.w;
            acc.x += s2 * g2.x; acc.y += s2 * g2.y; acc.z += s2 * g2.z; acc.w += s2 * g2.w;
            acc.x += s3 * g3.x; acc.y += s3 * g3.y; acc.z += s3 * g3.z; acc.w += s3 * g3.w;
            acc.x += s4 * g4.x; acc.y += s4 * g4.y; acc.z += s4 * g4.z; acc.w += s4 * g4.w;
            acc.x += s5 * g5.x; acc.y += s5 * g5.y; acc.z += s5 * g5.z; acc.w += s5 * g5.w;
            acc.x += s6 * g6.x; acc.y += s6 * g6.y; acc.z += s6 * g6.z; acc.w += s6 * g6.w;
            acc.x += s7 * g7.x; acc.y += s7 * g7.y; acc.z += s7 * g7.z; acc.w += s7 * g7.w;
        }

        if (sub == 1) red[cgrp * 64 + col4] = acc;
        __syncthreads();
        if (sub == 0) {
            float4 o = red[cgrp * 64 + col4];
            acc.x += o.x; acc.y += o.y; acc.z += o.z; acc.w += o.w;

            int cls = c0 + cgrp;
            float cnt = g_counts[cls];
            float4 tv = ((const float4*)g_t)[(size_t)cls * 64 + col4];
            float4 v = make_float4(0.f, 0.f, 0.f, 0.f);
            if (cnt > 0.0f) {
                float rc = 1.0f / cnt;
                v = make_float4((acc.x + tv.x) * rc, (acc.y + tv.y) * rc,
                                (acc.z + tv.z) * rc, (acc.w + tv.w) * rc);
            }
            ((float4*)proto)[(size_t)cls * 64 + col4] = v;
        }
        __threadfence();
        __syncthreads();
        if (tid == 0) atomicAdd(&g_flagC, 1u);
    } else {
        // ---- inter tile ----
        if (tid == 0) { while (atomicAdd(&g_flagC, 0u) < 500u) { } }
        __syncthreads();

        float4* pi = smem4;            // [16][64]
        float4* pj = smem4 + 1024;     // [16][64]
        int lin = b - 540;             // 0..3968
        int bx = lin % 63, by = lin / 63;
        int i0 = by * 16, j0 = bx * 16;

        const float4* p4 = (const float4*)proto;
#pragma unroll
        for (int l = 0; l < 4; l++) {
            int idx = tid + l * 256;         // 0..1023
            int r = idx >> 6, d = idx & 63;
            int gi = i0 + r, gj = j0 + r;
            pi[r * 64 + d] = (gi < NC) ? p4[gi * 64 + d] : make_float4(0.f, 0.f, 0.f, 0.f);
            pj[r * 64 + d] = (gj < NC) ? p4[gj * 64 + d] : make_float4(0.f, 0.f, 0.f, 0.f);
        }
        __syncthreads();

        int d = tid & 63;
        int p0 = tid >> 6;                   // 0..3
        float4* o4 = (float4*)inter;

        if (i0 + 16 <= NC && j0 + 16 <= NC) {
#pragma unroll 8
            for (int p = p0; p < 256; p += 4) {
                int il = p >> 4, jl = p & 15;
                float4 a = pj[jl * 64 + d];
                float4 bv = pi[il * 64 + d];
                float4 v = make_float4(a.x - bv.x, a.y - bv.y, a.z - bv.z, a.w - bv.w);
                __stcs(&o4[((size_t)(i0 + il) * NC + (j0 + jl)) * 64 + d], v);
            }
        } else {
            for (int p = p0; p < 256; p += 4) {
                int il = p >> 4, jl = p & 15;
                int i = i0 + il, j = j0 + jl;
                if (i < NC && j < NC) {
                    float4 a = pj[jl * 64 + d];
                    float4 bv = pi[il * 64 + d];
                    float4 v = make_float4(a.x - bv.x, a.y - bv.y, a.z - bv.z, a.w - bv.w);
                    __stcs(&o4[((size_t)i * NC + j) * 64 + d], v);
                }
            }
        }
    }
}

// ---------------------------------------------------------------
extern "C" void kernel_launch(void* const* d_in, const int* in_sizes, int n_in,
                              void* d_out, int out_size) {
    const float* x  = (const float*)d_in[0];   // [4096, 256]
    const float* lg = (const float*)d_in[1];   // [4096, 1000]
    float* out   = (float*)d_out;
    float* proto = out;                         // [1000, 256]
    float* inter = out + (size_t)NC * CH;       // [1000, 1000, 256]

    k_stage1<<<1845, 256>>>(x, lg);
    k_stage2<<<540 + 63 * 63, 256>>>(proto, inter);
}

// round 15
// speedup vs baseline: 1.0042x; 1.0042x over previous
#include <cuda_runtime.h>
#include <cstddef>

#define N_ROWS 4096
#define CH     256
#define NC     1000
#define NTILE  10      // upper-triangle 64x64 tiles of 256x256
#define NSPLIT 32      // K-splits of depth 128 over K=4096

// ---- scratch (static device globals; no runtime allocation) ----
__device__ float g_invn[N_ROWS];
__device__ float g_xn[N_ROWS * CH];                // D^-1 X (normalized rows)
__device__ float g_G[CH * CH];                     // full (mirrored) gram
__device__ float g_part[NTILE * NSPLIT * 64 * 64]; // 5.2 MB partial tiles
__device__ float g_s[NC * CH];                     // per-class sum invn_r * x_r
__device__ float g_t[NC * CH];                     // per-class sum x_r
__device__ float g_counts[NC];
__device__ unsigned int g_flagP;                   // prep-done (stage1 internal)
__device__ unsigned int g_flagR;                   // redG-done (gproto internal)

__constant__ int c_ti[NTILE] = {0,0,0,0,1,1,1,2,2,3};
__constant__ int c_tj[NTILE] = {0,1,2,3,1,2,3,2,3,3};

// ---------------------------------------------------------------
// K1: prep -> (gram partials | argmax+scatter), staged via flagP.
//  b in [0,512):      norms + write Xn rows (8 rows/block)       -> flagP++
//  b in [512,762):    zero g_s                                   -> flagP++
//  b in [762,1012):   zero g_t                                   -> flagP++
//  b == 1012:         zero counts, reset flagR                   -> flagP++
//  b in [1013,1333):  spin flagP==1013, gram 64x64 tile, K=128
//  b in [1333,1845):  spin flagP==1013, warp-per-row argmax + scatter
// Safe: 1013 prep blocks all fit in wave 1 (8 blocks/SM x 148 SM).
// ---------------------------------------------------------------
__global__ void __launch_bounds__(256) k_stage1(const float* __restrict__ x,
                                                const float* __restrict__ lg) {
    __shared__ float smem[2048];
    int b = blockIdx.x;
    int tid = threadIdx.x;

    if (b < 1013) {
        if (b < 512) {
            int warp = ((b << 8) + tid) >> 5;       // 0..4095
            int lane = tid & 31;
            const float4* p = (const float4*)(x + (size_t)warp * CH);
            float4 v0 = p[lane];
            float4 v1 = p[lane + 32];
            float ss = v0.x * v0.x + v0.y * v0.y + v0.z * v0.z + v0.w * v0.w
                     + v1.x * v1.x + v1.y * v1.y + v1.z * v1.z + v1.w * v1.w;
#pragma unroll
            for (int off = 16; off; off >>= 1)
                ss += __shfl_xor_sync(0xffffffffu, ss, off);
            float inv = rsqrtf(ss);
            float4* xn4 = (float4*)(g_xn + (size_t)warp * CH);
            xn4[lane]      = make_float4(v0.x * inv, v0.y * inv, v0.z * inv, v0.w * inv);
            xn4[lane + 32] = make_float4(v1.x * inv, v1.y * inv, v1.z * inv, v1.w * inv);
            if (lane == 0) g_invn[warp] = inv;
        } else if (b < 762) {
            ((float4*)g_s)[(b - 512) * 256 + tid] = make_float4(0.f, 0.f, 0.f, 0.f);
        } else if (b < 1012) {
            ((float4*)g_t)[(b - 762) * 256 + tid] = make_float4(0.f, 0.f, 0.f, 0.f);
        } else {
            for (int i = tid; i < NC; i += 256) g_counts[i] = 0.0f;
            if (tid == 0) g_flagR = 0u;
        }
        __threadfence();
        __syncthreads();
        if (tid == 0) atomicAdd(&g_flagP, 1u);
    } else if (b < 1333) {
        if (tid == 0) { while (atomicAdd(&g_flagP, 0u) < 1013u) { } }
        __syncthreads();

        float* As = smem;            // [16][64] : Xn[k][i-tile]
        float* Bs = smem + 1024;     // [16][64] : X [k][j-tile]
        int bb_ = b - 1013;
        int tile = bb_ >> 5;         // 0..9
        int k0 = (bb_ & 31) * 128;   // split * 128
        int i0 = c_ti[tile] * 64, j0 = c_tj[tile] * 64;
        int tx = tid & 15, ty = tid >> 4;

        float acc[4][4] = {};
#pragma unroll
        for (int kc = 0; kc < 128; kc += 16) {
#pragma unroll
            for (int l = 0; l < 4; l++) {
                int idx = tid + l * 256;          // 0..1023
                int kl = idx >> 6, col = idx & 63;
                int k = k0 + kc + kl;
                As[kl * 64 + col] = g_xn[(size_t)k * CH + i0 + col];
                Bs[kl * 64 + col] = x   [(size_t)k * CH + j0 + col];
            }
            __syncthreads();
            const float4* As4 = (const float4*)As;
            const float4* Bs4 = (const float4*)Bs;
#pragma unroll
            for (int kl = 0; kl < 16; kl++) {
                float4 a = As4[kl * 16 + ty];
                float4 bb = Bs4[kl * 16 + tx];
                acc[0][0] += a.x * bb.x; acc[0][1] += a.x * bb.y;
                acc[0][2] += a.x * bb.z; acc[0][3] += a.x * bb.w;
                acc[1][0] += a.y * bb.x; acc[1][1] += a.y * bb.y;
                acc[1][2] += a.y * bb.z; acc[1][3] += a.y * bb.w;
                acc[2][0] += a.z * bb.x; acc[2][1] += a.z * bb.y;
                acc[2][2] += a.z * bb.z; acc[2][3] += a.z * bb.w;
                acc[3][0] += a.w * bb.x; acc[3][1] += a.w * bb.y;
                acc[3][2] += a.w * bb.z; acc[3][3] += a.w * bb.w;
            }
            __syncthreads();
        }
        float4* p4 = (float4*)(g_part + (size_t)bb_ * 4096);
#pragma unroll
        for (int u = 0; u < 4; u++)
            p4[(ty * 4 + u) * 16 + tx] =
                make_float4(acc[u][0], acc[u][1], acc[u][2], acc[u][3]);
    } else {
        if (tid == 0) { while (atomicAdd(&g_flagP, 0u) < 1013u) { } }
        __syncthreads();

        // ---- warp-per-row argmax + scatter, 8 rows per block ----
        int row = ((b - 1333) << 3) + (tid >> 5);
        int lane = tid & 31;
        const float4* p = (const float4*)(lg + (size_t)row * NC);  // 250 float4
        float best = -3.4e38f;
        int   bi = 0;
#pragma unroll
        for (int i = 0; i < 8; i++) {
            int idx = lane + (i << 5);
            if (idx < 250) {
                float4 v = p[idx];
                int c = idx << 2;
                if (v.x > best) { best = v.x; bi = c; }
                if (v.y > best) { best = v.y; bi = c + 1; }
                if (v.z > best) { best = v.z; bi = c + 2; }
                if (v.w > best) { best = v.w; bi = c + 3; }
            }
        }
#pragma unroll
        for (int off = 16; off; off >>= 1) {
            float ov = __shfl_xor_sync(0xffffffffu, best, off);
            int   oi = __shfl_xor_sync(0xffffffffu, bi,   off);
            if (ov > best || (ov == best && oi < bi)) { best = ov; bi = oi; }
        }
        int cls = bi;
        float inv = g_invn[row];
        const float4* px = (const float4*)(x + (size_t)row * CH);
#pragma unroll
        for (int j = 0; j < 2; j++) {
            int idx4 = lane + (j << 5);           // 0..63
            float4 xv = px[idx4];
            int base = cls * CH + (idx4 << 2);
            atomicAdd(&g_s[base + 0], xv.x * inv);
            atomicAdd(&g_s[base + 1], xv.y * inv);
            atomicAdd(&g_s[base + 2], xv.z * inv);
            atomicAdd(&g_s[base + 3], xv.w * inv);
            atomicAdd(&g_t[base + 0], xv.x);
            atomicAdd(&g_t[base + 1], xv.y);
            atomicAdd(&g_t[base + 2], xv.z);
            atomicAdd(&g_t[base + 3], xv.w);
        }
        if (lane == 0) atomicAdd(&g_counts[cls], 1.0f);
    }
}

// ---------------------------------------------------------------
// K2: merged redG + proto, single launch (260 blocks x 1024 thr,
// all co-resident: <= 2 blocks/SM x 148 SMs).
//  b in [0,10):   reduce g_part -> g_G (+ mirror), then signal flagR.
//  b in [10,260): spin flagR==10, then proto GEMV:
//                 proto_c = (s_c @ G + t_c)/count.
// ---------------------------------------------------------------
__global__ void __launch_bounds__(1024) k_gproto(float* __restrict__ proto) {
    __shared__ float  s_sm[4 * 256];
    __shared__ float4 red[3 * 4 * 64];
    int b = blockIdx.x;
    int tid = threadIdx.x;

    if (b == 0 && tid == 0) g_flagP = 0u;   // reset for next graph replay

    if (b < 10) {
        int idx = b * 1024 + tid;                 // 0..10239
        int tile = idx >> 10;
        int p4i  = idx & 1023;
        int i0 = c_ti[tile] * 64, j0 = c_tj[tile] * 64;

        const float4* part4 = (const float4*)g_part;
        float4 sum = make_float4(0.f, 0.f, 0.f, 0.f);
#pragma unroll 8
        for (int s = 0; s < NSPLIT; s++) {
            float4 v = part4[(size_t)((tile << 5) + s) * 1024 + p4i];
            sum.x += v.x; sum.y += v.y; sum.z += v.z; sum.w += v.w;
        }
        int il = p4i >> 4;
        int jb = (p4i & 15) << 2;
        int i = i0 + il, j = j0 + jb;
        ((float4*)g_G)[(i * CH + j) >> 2] = sum;
        if (i0 != j0) {
            g_G[(j + 0) * CH + i] = sum.x;
            g_G[(j + 1) * CH + i] = sum.y;
            g_G[(j + 2) * CH + i] = sum.z;
            g_G[(j + 3) * CH + i] = sum.w;
        }
        __threadfence();
        __syncthreads();
        if (tid == 0) atomicAdd(&g_flagR, 1u);
    } else {
        int c0 = (b - 10) * 4;
        int cgrp = tid >> 8;          // 0..3  class within block
        int sub  = (tid >> 6) & 3;    // k-quarter
        int col4 = tid & 63;          // float4 column group

        s_sm[tid & 1023] = g_s[(size_t)c0 * CH + (tid & 1023)];
        if (tid == 0) {
            while (atomicAdd(&g_flagR, 0u) < 10u) { }
        }
        __syncthreads();

        const float4* Gp = (const float4*)g_G + (size_t)(sub * 64) * 64 + col4;
        const float*  sr = s_sm + cgrp * 256 + sub * 64;
        float4 acc = make_float4(0.f, 0.f, 0.f, 0.f);
#pragma unroll
        for (int kb = 0; kb < 64; kb += 8) {
            float4 g0 = Gp[(kb + 0) * 64];
            float4 g1 = Gp[(kb + 1) * 64];
            float4 g2 = Gp[(kb + 2) * 64];
            float4 g3 = Gp[(kb + 3) * 64];
            float4 g4 = Gp[(kb + 4) * 64];
            float4 g5 = Gp[(kb + 5) * 64];
            float4 g6 = Gp[(kb + 6) * 64];
            float4 g7 = Gp[(kb + 7) * 64];
            float s0 = sr[kb + 0], s1 = sr[kb + 1], s2 = sr[kb + 2], s3 = sr[kb + 3];
            float s4 = sr[kb + 4], s5 = sr[kb + 5], s6 = sr[kb + 6], s7 = sr[kb + 7];
            acc.x += s0 * g0.x; acc.y += s0 * g0.y; acc.z += s0 * g0.z; acc.w += s0 * g0.w;
            acc.x += s1 * g1.x; acc.y += s1 * g1.y; acc.z += s1 * g1.z; acc.w += s1 * g1.w;
            acc.x += s2 * g2.x; acc.y += s2 * g2.y; acc.z += s2 * g2.z; acc.w += s2 * g2.w;
            acc.x += s3 * g3.x; acc.y += s3 * g3.y; acc.z += s3 * g3.z; acc.w += s3 * g3.w;
            acc.x += s4 * g4.x; acc.y += s4 * g4.y; acc.z += s4 * g4.z; acc.w += s4 * g4.w;
            acc.x += s5 * g5.x; acc.y += s5 * g5.y; acc.z += s5 * g5.z; acc.w += s5 * g5.w;
            acc.x += s6 * g6.x; acc.y += s6 * g6.y; acc.z += s6 * g6.z; acc.w += s6 * g6.w;
            acc.x += s7 * g7.x; acc.y += s7 * g7.y; acc.z += s7 * g7.z; acc.w += s7 * g7.w;
        }

        if (sub > 0) red[(sub - 1) * 256 + cgrp * 64 + col4] = acc;
        __syncthreads();
        if (sub == 0) {
            float4 o0 = red[0 * 256 + cgrp * 64 + col4];
            float4 o1 = red[1 * 256 + cgrp * 64 + col4];
            float4 o2 = red[2 * 256 + cgrp * 64 + col4];
            acc.x += o0.x + o1.x + o2.x;
            acc.y += o0.y + o1.y + o2.y;
            acc.z += o0.z + o1.z + o2.z;
            acc.w += o0.w + o1.w + o2.w;

            int cls = c0 + cgrp;
            float cnt = g_counts[cls];
            float4 tv = ((const float4*)g_t)[(size_t)cls * 64 + col4];
            float4 v = make_float4(0.f, 0.f, 0.f, 0.f);
            if (cnt > 0.0f) {
                float rc = 1.0f / cnt;
                v = make_float4((acc.x + tv.x) * rc, (acc.y + tv.y) * rc,
                                (acc.z + tv.z) * rc, (acc.w + tv.w) * rc);
            }
            ((float4*)proto)[(size_t)cls * 64 + col4] = v;
        }
    }
}

// ---------------------------------------------------------------
// K3: inter[i][j][:] = proto[j] - proto[i]   (1.02 GB, write-bound).
// PURE kernel — owns the whole chip; 87% DRAM measured.
// ---------------------------------------------------------------
__global__ void k_inter(const float* __restrict__ proto, float* __restrict__ inter) {
    __shared__ float4 pi[16][64];
    __shared__ float4 pj[16][64];
    int i0 = blockIdx.y * 16, j0 = blockIdx.x * 16;
    int tid = threadIdx.x;               // 256 threads

    const float4* p4 = (const float4*)proto;
#pragma unroll
    for (int l = 0; l < 4; l++) {
        int idx = tid + l * 256;         // 0..1023
        int r = idx >> 6, d = idx & 63;
        int gi = i0 + r, gj = j0 + r;
        pi[r][d] = (gi < NC) ? p4[gi * 64 + d] : make_float4(0.f, 0.f, 0.f, 0.f);
        pj[r][d] = (gj < NC) ? p4[gj * 64 + d] : make_float4(0.f, 0.f, 0.f, 0.f);
    }
    __syncthreads();

    int d = tid & 63;
    int p0 = tid >> 6;                   // 0..3
    float4* o4 = (float4*)inter;

    if (i0 + 16 <= NC && j0 + 16 <= NC) {
#pragma unroll 8
        for (int p = p0; p < 256; p += 4) {
            int il = p >> 4, jl = p & 15;
            float4 a = pj[jl][d];
            float4 bv = pi[il][d];
            float4 v = make_float4(a.x - bv.x, a.y - bv.y, a.z - bv.z, a.w - bv.w);
            __stcs(&o4[((size_t)(i0 + il) * NC + (j0 + jl)) * 64 + d], v);
        }
    } else {
        for (int p = p0; p < 256; p += 4) {
            int il = p >> 4, jl = p & 15;
            int i = i0 + il, j = j0 + jl;
            if (i < NC && j < NC) {
                float4 a = pj[jl][d];
                float4 bv = pi[il][d];
                float4 v = make_float4(a.x - bv.x, a.y - bv.y, a.z - bv.z, a.w - bv.w);
                __stcs(&o4[((size_t)i * NC + j) * 64 + d], v);
            }
        }
    }
}

// ---------------------------------------------------------------
extern "C" void kernel_launch(void* const* d_in, const int* in_sizes, int n_in,
                              void* d_out, int out_size) {
    const float* x  = (const float*)d_in[0];   // [4096, 256]
    const float* lg = (const float*)d_in[1];   // [4096, 1000]
    float* out   = (float*)d_out;
    float* proto = out;                         // [1000, 256]
    float* inter = out + (size_t)NC * CH;       // [1000, 1000, 256]

    k_stage1<<<1845, 256>>>(x, lg);
    k_gproto<<<260, 1024>>>(proto);
    k_inter <<<dim3(63, 63), 256>>>(proto, inter);
}

// round 16
// speedup vs baseline: 1.0557x; 1.0512x over previous
#include <cuda_runtime.h>
#include <cstddef>

#define N_ROWS 4096
#define CH     256
#define NC     1000
#define NTILE  10      // upper-triangle 64x64 tiles of 256x256
#define NSPLIT 32      // K-splits of depth 128 over K=4096

// ---- scratch (static device globals; no runtime allocation) ----
__device__ float g_invn[N_ROWS];
__device__ float g_xn[N_ROWS * CH];                // D^-1 X (normalized rows)
__device__ float g_G[CH * CH];                     // full (mirrored) gram
__device__ float g_part[NTILE * NSPLIT * 64 * 64]; // 5.2 MB partial tiles
__device__ float g_s[NC * CH];                     // per-class sum invn_r * x_r
__device__ float g_t[NC * CH];                     // per-class sum x_r
__device__ float g_counts[NC];
__device__ unsigned int g_flagR;                   // redG-done (gproto internal)

__constant__ int c_ti[NTILE] = {0,0,0,0,1,1,1,2,2,3};
__constant__ int c_tj[NTILE] = {0,1,2,3,1,2,3,2,3,3};

// ---------------------------------------------------------------
// K1: prep — norms (+ write normalized rows) + zero class accumulators
// ---------------------------------------------------------------
__global__ void k_prep(const float* __restrict__ x) {
    int b = blockIdx.x;
    int tid = threadIdx.x;
    if (b < 512) {
        int warp = ((b << 8) + tid) >> 5;       // 0..4095
        int lane = tid & 31;
        const float4* p = (const float4*)(x + (size_t)warp * CH);
        float4 v0 = p[lane];
        float4 v1 = p[lane + 32];
        float ss = v0.x * v0.x + v0.y * v0.y + v0.z * v0.z + v0.w * v0.w
                 + v1.x * v1.x + v1.y * v1.y + v1.z * v1.z + v1.w * v1.w;
#pragma unroll
        for (int off = 16; off; off >>= 1)
            ss += __shfl_xor_sync(0xffffffffu, ss, off);
        float inv = rsqrtf(ss);
        float4* xn4 = (float4*)(g_xn + (size_t)warp * CH);
        xn4[lane]      = make_float4(v0.x * inv, v0.y * inv, v0.z * inv, v0.w * inv);
        xn4[lane + 32] = make_float4(v1.x * inv, v1.y * inv, v1.z * inv, v1.w * inv);
        if (lane == 0) g_invn[warp] = inv;
    } else if (b < 762) {
        ((float4*)g_s)[(b - 512) * 256 + tid] = make_float4(0.f, 0.f, 0.f, 0.f);
    } else if (b < 1012) {
        ((float4*)g_t)[(b - 762) * 256 + tid] = make_float4(0.f, 0.f, 0.f, 0.f);
    } else {
        for (int i = tid; i < NC; i += 256) g_counts[i] = 0.0f;
        if (tid == 0) g_flagR = 0u;
    }
}

// ---------------------------------------------------------------
// K2: fused gram-partials + (argmax -> class scatter).
//  b in [0,320):       G-partial = Xn^T X over 64x64 tile, K-depth 128.
//  b in [320,320+512): warp-per-row argmax + scatter into g_s / g_t.
// ---------------------------------------------------------------
__global__ void k_fused(const float* __restrict__ x,
                        const float* __restrict__ lg) {
    __shared__ float smem[2048];
    int b = blockIdx.x;
    int tid = threadIdx.x;

    if (b < NTILE * NSPLIT) {
        float* As = smem;            // [16][64] : Xn[k][i-tile]
        float* Bs = smem + 1024;     // [16][64] : X [k][j-tile]
        int tile = b >> 5;           // 0..9
        int k0 = (b & 31) * 128;     // split * 128
        int i0 = c_ti[tile] * 64, j0 = c_tj[tile] * 64;
        int tx = tid & 15, ty = tid >> 4;

        float acc[4][4] = {};
#pragma unroll
        for (int kc = 0; kc < 128; kc += 16) {
#pragma unroll
            for (int l = 0; l < 4; l++) {
                int idx = tid + l * 256;          // 0..1023
                int kl = idx >> 6, col = idx & 63;
                int k = k0 + kc + kl;
                As[kl * 64 + col] = g_xn[(size_t)k * CH + i0 + col];
                Bs[kl * 64 + col] = x   [(size_t)k * CH + j0 + col];
            }
            __syncthreads();
            const float4* As4 = (const float4*)As;
            const float4* Bs4 = (const float4*)Bs;
#pragma unroll
            for (int kl = 0; kl < 16; kl++) {
                float4 a = As4[kl * 16 + ty];
                float4 bb = Bs4[kl * 16 + tx];
                acc[0][0] += a.x * bb.x; acc[0][1] += a.x * bb.y;
                acc[0][2] += a.x * bb.z; acc[0][3] += a.x * bb.w;
                acc[1][0] += a.y * bb.x; acc[1][1] += a.y * bb.y;
                acc[1][2] += a.y * bb.z; acc[1][3] += a.y * bb.w;
                acc[2][0] += a.z * bb.x; acc[2][1] += a.z * bb.y;
                acc[2][2] += a.z * bb.z; acc[2][3] += a.z * bb.w;
                acc[3][0] += a.w * bb.x; acc[3][1] += a.w * bb.y;
                acc[3][2] += a.w * bb.z; acc[3][3] += a.w * bb.w;
            }
            __syncthreads();
        }
        float4* p4 = (float4*)(g_part + (size_t)b * 4096);
#pragma unroll
        for (int u = 0; u < 4; u++)
            p4[(ty * 4 + u) * 16 + tx] =
                make_float4(acc[u][0], acc[u][1], acc[u][2], acc[u][3]);
    } else {
        // ---- warp-per-row argmax + scatter, 8 rows per block ----
        int row = ((b - NTILE * NSPLIT) << 3) + (tid >> 5);
        int lane = tid & 31;
        const float4* p = (const float4*)(lg + (size_t)row * NC);  // 250 float4
        float best = -3.4e38f;
        int   bi = 0;
#pragma unroll
        for (int i = 0; i < 8; i++) {
            int idx = lane + (i << 5);
            if (idx < 250) {
                float4 v = p[idx];
                int c = idx << 2;
                if (v.x > best) { best = v.x; bi = c; }
                if (v.y > best) { best = v.y; bi = c + 1; }
                if (v.z > best) { best = v.z; bi = c + 2; }
                if (v.w > best) { best = v.w; bi = c + 3; }
            }
        }
#pragma unroll
        for (int off = 16; off; off >>= 1) {
            float ov = __shfl_xor_sync(0xffffffffu, best, off);
            int   oi = __shfl_xor_sync(0xffffffffu, bi,   off);
            if (ov > best || (ov == best && oi < bi)) { best = ov; bi = oi; }
        }
        int cls = bi;
        float inv = g_invn[row];
        const float4* px = (const float4*)(x + (size_t)row * CH);
#pragma unroll
        for (int j = 0; j < 2; j++) {
            int idx4 = lane + (j << 5);           // 0..63
            float4 xv = px[idx4];
            int base = cls * CH + (idx4 << 2);
            atomicAdd(&g_s[base + 0], xv.x * inv);
            atomicAdd(&g_s[base + 1], xv.y * inv);
            atomicAdd(&g_s[base + 2], xv.z * inv);
            atomicAdd(&g_s[base + 3], xv.w * inv);
            atomicAdd(&g_t[base + 0], xv.x);
            atomicAdd(&g_t[base + 1], xv.y);
            atomicAdd(&g_t[base + 2], xv.z);
            atomicAdd(&g_t[base + 3], xv.w);
        }
        if (lane == 0) atomicAdd(&g_counts[cls], 1.0f);
    }
}

// ---------------------------------------------------------------
// K3: merged redG + proto, single launch (260 blocks x 1024 thr).
//  b in [0,10):   reduce g_part -> g_G (+ mirror), then signal flagR.
//  b in [10,260): spin flagR==10, then proto_c = (s_c @ G + t_c)/count.
// ---------------------------------------------------------------
__global__ void __launch_bounds__(1024) k_gproto(float* __restrict__ proto) {
    __shared__ float  s_sm[4 * 256];
    __shared__ float4 red[3 * 4 * 64];
    int b = blockIdx.x;
    int tid = threadIdx.x;

    if (b < 10) {
        int idx = b * 1024 + tid;                 // 0..10239
        int tile = idx >> 10;
        int p4i  = idx & 1023;
        int i0 = c_ti[tile] * 64, j0 = c_tj[tile] * 64;

        const float4* part4 = (const float4*)g_part;
        float4 sum = make_float4(0.f, 0.f, 0.f, 0.f);
#pragma unroll 8
        for (int s = 0; s < NSPLIT; s++) {
            float4 v = part4[(size_t)((tile << 5) + s) * 1024 + p4i];
            sum.x += v.x; sum.y += v.y; sum.z += v.z; sum.w += v.w;
        }
        int il = p4i >> 4;
        int jb = (p4i & 15) << 2;
        int i = i0 + il, j = j0 + jb;
        ((float4*)g_G)[(i * CH + j) >> 2] = sum;
        if (i0 != j0) {
            g_G[(j + 0) * CH + i] = sum.x;
            g_G[(j + 1) * CH + i] = sum.y;
            g_G[(j + 2) * CH + i] = sum.z;
            g_G[(j + 3) * CH + i] = sum.w;
        }
        __threadfence();
        __syncthreads();
        if (tid == 0) atomicAdd(&g_flagR, 1u);
    } else {
        int c0 = (b - 10) * 4;
        int cgrp = tid >> 8;          // 0..3  class within block
        int sub  = (tid >> 6) & 3;    // k-quarter
        int col4 = tid & 63;          // float4 column group

        s_sm[tid & 1023] = g_s[(size_t)c0 * CH + (tid & 1023)];
        if (tid == 0) {
            while (atomicAdd(&g_flagR, 0u) < 10u) { }
        }
        __syncthreads();

        const float4* Gp = (const float4*)g_G + (size_t)(sub * 64) * 64 + col4;
        const float*  sr = s_sm + cgrp * 256 + sub * 64;
        float4 acc = make_float4(0.f, 0.f, 0.f, 0.f);
#pragma unroll
        for (int kb = 0; kb < 64; kb += 8) {
            float4 g0 = Gp[(kb + 0) * 64];
            float4 g1 = Gp[(kb + 1) * 64];
            float4 g2 = Gp[(kb + 2) * 64];
            float4 g3 = Gp[(kb + 3) * 64];
            float4 g4 = Gp[(kb + 4) * 64];
            float4 g5 = Gp[(kb + 5) * 64];
            float4 g6 = Gp[(kb + 6) * 64];
            float4 g7 = Gp[(kb + 7) * 64];
            float s0 = sr[kb + 0], s1 = sr[kb + 1], s2 = sr[kb + 2], s3 = sr[kb + 3];
            float s4 = sr[kb + 4], s5 = sr[kb + 5], s6 = sr[kb + 6], s7 = sr[kb + 7];
            acc.x += s0 * g0.x; acc.y += s0 * g0.y; acc.z += s0 * g0.z; acc.w += s0 * g0.w;
            acc.x += s1 * g1.x; acc.y += s1 * g1.y; acc.z += s1 * g1.z; acc.w += s1 * g1.w;
            acc.x += s2 * g2.x; acc.y += s2 * g2.y; acc.z += s2 * g2.z; acc.w += s2 * g2.w;
            acc.x += s3 * g3.x; acc.y += s3 * g3.y; acc.z += s3 * g3.z; acc.w += s3 * g3.w;
            acc.x += s4 * g4.x; acc.y += s4 * g4.y; acc.z += s4 * g4.z; acc.w += s4 * g4.w;
            acc.x += s5 * g5.x; acc.y += s5 * g5.y; acc.z += s5 * g5.z; acc.w += s5 * g5.w;
            acc.x += s6 * g6.x; acc.y += s6 * g6.y; acc.z += s6 * g6.z; acc.w += s6 * g6.w;
            acc.x += s7 * g7.x; acc.y += s7 * g7.y; acc.z += s7 * g7.z; acc.w += s7 * g7.w;
        }

        if (sub > 0) red[(sub - 1) * 256 + cgrp * 64 + col4] = acc;
        __syncthreads();
        if (sub == 0) {
            float4 o0 = red[0 * 256 + cgrp * 64 + col4];
            float4 o1 = red[1 * 256 + cgrp * 64 + col4];
            float4 o2 = red[2 * 256 + cgrp * 64 + col4];
            acc.x += o0.x + o1.x + o2.x;
            acc.y += o0.y + o1.y + o2.y;
            acc.z += o0.z + o1.z + o2.z;
            acc.w += o0.w + o1.w + o2.w;

            int cls = c0 + cgrp;
            float cnt = g_counts[cls];
            float4 tv = ((const float4*)g_t)[(size_t)cls * 64 + col4];
            float4 v = make_float4(0.f, 0.f, 0.f, 0.f);
            if (cnt > 0.0f) {
                float rc = 1.0f / cnt;
                v = make_float4((acc.x + tv.x) * rc, (acc.y + tv.y) * rc,
                                (acc.z + tv.z) * rc, (acc.w + tv.w) * rc);
            }
            ((float4*)proto)[(size_t)cls * 64 + col4] = v;
        }
    }
}

// ---------------------------------------------------------------
// K4: inter[i][j][:] = proto[j] - proto[i]   (1.02 GB, write-bound).
// 32x16 (i,j) tiles, 512 threads, 48 KB smem -> 4 blocks/SM, 64 warps/SM.
// ---------------------------------------------------------------
__global__ void __launch_bounds__(512) k_inter(const float* __restrict__ proto,
                                               float* __restrict__ inter) {
    __shared__ float4 pi[32 * 64];
    __shared__ float4 pj[16 * 64];
    int i0 = blockIdx.y * 32, j0 = blockIdx.x * 16;
    int tid = threadIdx.x;               // 512 threads

    const float4* p4 = (const float4*)proto;
#pragma unroll
    for (int l = 0; l < 4; l++) {
        int idx = tid + l * 512;         // 0..2047
        int r = idx >> 6, d = idx & 63;
        int gi = i0 + r;
        pi[idx] = (gi < NC) ? p4[gi * 64 + d] : make_float4(0.f, 0.f, 0.f, 0.f);
    }
#pragma unroll
    for (int l = 0; l < 2; l++) {
        int idx = tid + l * 512;         // 0..1023
        int r = idx >> 6, d = idx & 63;
        int gj = j0 + r;
        pj[idx] = (gj < NC) ? p4[gj * 64 + d] : make_float4(0.f, 0.f, 0.f, 0.f);
    }
    __syncthreads();

    int d = tid & 63;
    int p0 = tid >> 6;                   // 0..7
    float4* o4 = (float4*)inter;

    if (i0 + 32 <= NC && j0 + 16 <= NC) {
#pragma unroll 8
        for (int p = p0; p < 512; p += 8) {
            int il = p >> 4, jl = p & 15;
            float4 a = pj[jl * 64 + d];
            float4 bv = pi[il * 64 + d];
            float4 v = make_float4(a.x - bv.x, a.y - bv.y, a.z - bv.z, a.w - bv.w);
            __stcs(&o4[((size_t)(i0 + il) * NC + (j0 + jl)) * 64 + d], v);
        }
    } else {
        for (int p = p0; p < 512; p += 8) {
            int il = p >> 4, jl = p & 15;
            int i = i0 + il, j = j0 + jl;
            if (i < NC && j < NC) {
                float4 a = pj[jl * 64 + d];
                float4 bv = pi[il * 64 + d];
                float4 v = make_float4(a.x - bv.x, a.y - bv.y, a.z - bv.z, a.w - bv.w);
                __stcs(&o4[((size_t)i * NC + j) * 64 + d], v);
            }
        }
    }
}

// ---------------------------------------------------------------
extern "C" void kernel_launch(void* const* d_in, const int* in_sizes, int n_in,
                              void* d_out, int out_size) {
    const float* x  = (const float*)d_in[0];   // [4096, 256]
    const float* lg = (const float*)d_in[1];   // [4096, 1000]
    float* out   = (float*)d_out;
    float* proto = out;                         // [1000, 256]
    float* inter = out + (size_t)NC * CH;       // [1000, 1000, 256]

    k_prep  <<<1013, 256>>>(x);
    k_fused <<<NTILE * NSPLIT + 512, 256>>>(x, lg);
    k_gproto<<<260, 1024>>>(proto);
    k_inter <<<dim3(63, 32), 512>>>(proto, inter);
}